// round 4
// baseline (speedup 1.0000x reference)
#include <cuda_runtime.h>

#define B_   256
#define T_   250
#define NS   2048
#define H_   256
#define G3   768
#define NSEL 50
#define UBv  0.1f
#define RITER 32

// ---------------- scratch (device globals; no runtime alloc) ----------------
__device__ float g_xg[(size_t)T_ * B_ * G3];     // xg0, later reused as xg1
__device__ float g_hseq[(size_t)T_ * B_ * H_];   // layer-0 hidden sequence [t][b][h]
__device__ float g_h1[2 * B_ * H_];              // layer-1 ping-pong
__device__ float g_att[B_ * NS];
__device__ float g_log[B_ * NS];

__device__ __forceinline__ float sigmf(float x) { return 1.f / (1.f + expf(-x)); }

// ============================================================================
// fp32 GEMM:  C[M,N] = act( A'[M,K] @ W[N,K]^T + bias[N] )
// permute=1: A row for output row m (= t*256+b) is x row b*250+t.
// BM=128, BN=64, BK=16, 256 threads, 8x4 micro-tile, double-buffered smem.
// ============================================================================
#define BM 128
#define BN 64
#define BK 16

__device__ __forceinline__ void gemm_tile_compute(
    const float (*__restrict__ As)[BM], const float (*__restrict__ Ws)[BN],
    float acc[8][4], int tm, int tn)
{
#pragma unroll
    for (int k = 0; k < BK; ++k) {
        float a[8], bb[4];
        *(float4*)&a[0] = *(const float4*)&As[k][tm * 8];
        *(float4*)&a[4] = *(const float4*)&As[k][tm * 8 + 4];
        *(float4*)&bb[0] = *(const float4*)&Ws[k][tn * 4];
#pragma unroll
        for (int i = 0; i < 8; ++i)
#pragma unroll
            for (int j = 0; j < 4; ++j)
                acc[i][j] = fmaf(a[i], bb[j], acc[i][j]);
    }
}

__global__ void __launch_bounds__(256) gemm_kernel(
    const float* __restrict__ A, const float* __restrict__ W,
    const float* __restrict__ bias, float* __restrict__ C,
    int M, int N, int K, int permute, int act)
{
    __shared__ float As[2][BK][BM];
    __shared__ float Ws[2][BK][BN];
    const int tid = threadIdx.x;
    const int m0 = blockIdx.y * BM;
    const int n0 = blockIdx.x * BN;

    const int lr = tid >> 2;          // 0..63
    const int lk = (tid & 3) << 2;    // 0,4,8,12

    const int mrow0 = m0 + lr;
    const int mrow1 = m0 + lr + 64;
    const long long arow0 = permute ? ((long long)(mrow0 & 255) * T_ + (mrow0 >> 8)) : (long long)mrow0;
    const long long arow1 = permute ? ((long long)(mrow1 & 255) * T_ + (mrow1 >> 8)) : (long long)mrow1;
    const float* pa0 = A + arow0 * K + lk;
    const float* pa1 = A + arow1 * K + lk;
    const float* pw  = W + (long long)(n0 + lr) * K + lk;

    const int tm = tid >> 4;   // 0..15
    const int tn = tid & 15;   // 0..15

    float acc[8][4];
#pragma unroll
    for (int i = 0; i < 8; ++i)
#pragma unroll
        for (int j = 0; j < 4; ++j) acc[i][j] = 0.f;

    {   // chunk 0
        float4 a0 = *(const float4*)pa0;
        float4 a1 = *(const float4*)pa1;
        float4 wv = *(const float4*)pw;
        float av0[4] = {a0.x, a0.y, a0.z, a0.w};
        float av1[4] = {a1.x, a1.y, a1.z, a1.w};
        float wvv[4] = {wv.x, wv.y, wv.z, wv.w};
#pragma unroll
        for (int j = 0; j < 4; ++j) {
            As[0][lk + j][lr]      = av0[j];
            As[0][lk + j][lr + 64] = av1[j];
            Ws[0][lk + j][lr]      = wvv[j];
        }
    }
    __syncthreads();

    const int nCh = K / BK;
    for (int c = 1; c < nCh; ++c) {
        const int off = c * BK;
        float4 na0 = *(const float4*)(pa0 + off);
        float4 na1 = *(const float4*)(pa1 + off);
        float4 nw  = *(const float4*)(pw + off);

        gemm_tile_compute(As[(c - 1) & 1], Ws[(c - 1) & 1], acc, tm, tn);

        const int wb = c & 1;
        float av0[4] = {na0.x, na0.y, na0.z, na0.w};
        float av1[4] = {na1.x, na1.y, na1.z, na1.w};
        float wvv[4] = {nw.x, nw.y, nw.z, nw.w};
#pragma unroll
        for (int j = 0; j < 4; ++j) {
            As[wb][lk + j][lr]      = av0[j];
            As[wb][lk + j][lr + 64] = av1[j];
            Ws[wb][lk + j][lr]      = wvv[j];
        }
        __syncthreads();
    }
    gemm_tile_compute(As[(nCh - 1) & 1], Ws[(nCh - 1) & 1], acc, tm, tn);

#pragma unroll
    for (int i = 0; i < 8; ++i) {
        const int m = m0 + tm * 8 + i;
        float v[4];
#pragma unroll
        for (int j = 0; j < 4; ++j) {
            float t = acc[i][j] + bias[n0 + tn * 4 + j];
            if (act == 1)      t = sigmf(t);
            else if (act == 2) t = t * sigmf(t);
            v[j] = t;
        }
        float4 o; o.x = v[0]; o.y = v[1]; o.z = v[2]; o.w = v[3];
        *(float4*)&C[(long long)m * N + n0 + tn * 4] = o;
    }
}

// ============================================================================
// GRU step: h_out = gates(h_in @ Whh^T + bhh, xg_t, h_in).   h_in==null -> h=0
// Grid (16,8), 128 threads. Block: 16 batch rows x 32 h-cols (96 gemm cols).
// ============================================================================
__device__ __forceinline__ void gru_chunk_compute(
    const float (*__restrict__ shh)[32], const float (*__restrict__ shw)[100],
    float acc[3][4], int rg, int hc)
{
#pragma unroll
    for (int k4 = 0; k4 < 8; ++k4) {
        float a[4][4];
#pragma unroll
        for (int i = 0; i < 4; ++i)
            *(float4*)a[i] = *(const float4*)&shh[rg * 4 + i][k4 * 4];
#pragma unroll
        for (int j = 0; j < 4; ++j) {
            const int k = k4 * 4 + j;
            const float wr = shw[k][hc];
            const float wz = shw[k][32 + hc];
            const float wn = shw[k][64 + hc];
#pragma unroll
            for (int i = 0; i < 4; ++i) {
                acc[0][i] = fmaf(a[i][j], wr, acc[0][i]);
                acc[1][i] = fmaf(a[i][j], wz, acc[1][i]);
                acc[2][i] = fmaf(a[i][j], wn, acc[2][i]);
            }
        }
    }
}

__global__ void __launch_bounds__(128) gru_step_kernel(
    const float* __restrict__ h_in,
    const float* __restrict__ Whh, const float* __restrict__ bhh,
    const float* __restrict__ xg_t, float* __restrict__ h_out)
{
    __shared__ float sh_h[2][16][32];
    __shared__ float sh_w[2][32][100];
    const int tid = threadIdx.x;
    const int b0 = blockIdx.x * 16;
    const int h0 = blockIdx.y * 32;
    const int hc = tid & 31;
    const int rg = tid >> 5;

    float acc[3][4];
#pragma unroll
    for (int g = 0; g < 3; ++g)
#pragma unroll
        for (int i = 0; i < 4; ++i) acc[g][i] = 0.f;

    if (h_in) {
        const int hr_ = tid >> 3;        // 0..15
        const int hk  = (tid & 7) << 2;  // 0..28
        {
            float4 hv = *(const float4*)(h_in + (long long)(b0 + hr_) * H_ + hk);
            *(float4*)&sh_h[0][hr_][hk] = hv;
#pragma unroll
            for (int q = 0; q < 6; ++q) {
                const int idx = tid + 128 * q;
                const int grow = idx >> 3;               // 0..95
                const int kq = (idx & 7) << 2;
                const int wrow = (grow >> 5) * H_ + h0 + (grow & 31);
                float4 wv = *(const float4*)(Whh + (long long)wrow * H_ + kq);
                sh_w[0][kq + 0][grow] = wv.x;
                sh_w[0][kq + 1][grow] = wv.y;
                sh_w[0][kq + 2][grow] = wv.z;
                sh_w[0][kq + 3][grow] = wv.w;
            }
        }
        __syncthreads();

        for (int kc = 1; kc < 8; ++kc) {
            const int k0 = kc * 32;
            float4 nh = *(const float4*)(h_in + (long long)(b0 + hr_) * H_ + k0 + hk);
            float4 nw[6];
#pragma unroll
            for (int q = 0; q < 6; ++q) {
                const int idx = tid + 128 * q;
                const int grow = idx >> 3;
                const int kq = (idx & 7) << 2;
                const int wrow = (grow >> 5) * H_ + h0 + (grow & 31);
                nw[q] = *(const float4*)(Whh + (long long)wrow * H_ + k0 + kq);
            }
            gru_chunk_compute(sh_h[(kc - 1) & 1], sh_w[(kc - 1) & 1], acc, rg, hc);
            const int wb = kc & 1;
            *(float4*)&sh_h[wb][hr_][hk] = nh;
#pragma unroll
            for (int q = 0; q < 6; ++q) {
                const int idx = tid + 128 * q;
                const int grow = idx >> 3;
                const int kq = (idx & 7) << 2;
                sh_w[wb][kq + 0][grow] = nw[q].x;
                sh_w[wb][kq + 1][grow] = nw[q].y;
                sh_w[wb][kq + 2][grow] = nw[q].z;
                sh_w[wb][kq + 3][grow] = nw[q].w;
            }
            __syncthreads();
        }
        gru_chunk_compute(sh_h[1], sh_w[1], acc, rg, hc);
    }

    const int hg = h0 + hc;
    const float br = bhh[hg], bz = bhh[H_ + hg], bn = bhh[2 * H_ + hg];
#pragma unroll
    for (int i = 0; i < 4; ++i) {
        const int b = b0 + rg * 4 + i;
        const float* xr = xg_t + (long long)b * G3;
        const float r = sigmf(xr[hg] + acc[0][i] + br);
        const float z = sigmf(xr[H_ + hg] + acc[1][i] + bz);
        const float n = tanhf(xr[2 * H_ + hg] + r * (acc[2][i] + bn));
        const float hold = h_in ? h_in[(long long)b * H_ + hg] : 0.f;
        h_out[(long long)b * H_ + hg] = (1.f - z) * n + z * hold;
    }
}

// ============================================================================
// Finalize per batch row: top-50 -> mask; softmax; mask+normalize; rebalance.
// ============================================================================
__global__ void __launch_bounds__(256) finalize_kernel(
    const float* __restrict__ att, const float* __restrict__ logits,
    float* __restrict__ out)
{
    __shared__ float a_s[NS];          // att, then "old"
    __shared__ float w_s[NS];          // logits -> weights
    __shared__ unsigned char m_s[NS];
    __shared__ float rf[256];
    __shared__ float rb[256];
    __shared__ int   ri[256];
    __shared__ float sc[8];

    const int b = blockIdx.x;
    const int tid = threadIdx.x;

    for (int n = tid; n < NS; n += 256) {
        a_s[n] = att[(long long)b * NS + n];
        w_s[n] = logits[(long long)b * NS + n];
        m_s[n] = 0;
    }
    if (tid == 0) sc[4] = 0.f;
    __syncthreads();

    // ---- top-50 ----
    for (int it = 0; it < NSEL; ++it) {
        float bv = -3.402823466e38f; int bi = 0x7fffffff;
        for (int n = tid; n < NS; n += 256) {
            float v = a_s[n];
            if (v > bv) { bv = v; bi = n; }
        }
        rf[tid] = bv; ri[tid] = bi;
        __syncthreads();
        for (int s = 128; s > 0; s >>= 1) {
            if (tid < s) {
                float v2 = rf[tid + s]; int i2 = ri[tid + s];
                if (v2 > rf[tid] || (v2 == rf[tid] && i2 < ri[tid])) { rf[tid] = v2; ri[tid] = i2; }
            }
            __syncthreads();
        }
        if (tid == 0) { m_s[ri[0]] = 1; a_s[ri[0]] = -3.402823466e38f; }
        __syncthreads();
    }

    // ---- softmax(logits) ----
    float lm = -3.402823466e38f;
    for (int n = tid; n < NS; n += 256) lm = fmaxf(lm, w_s[n]);
    rf[tid] = lm; __syncthreads();
    for (int s = 128; s > 0; s >>= 1) { if (tid < s) rf[tid] = fmaxf(rf[tid], rf[tid + s]); __syncthreads(); }
    const float Mx = rf[0];
    __syncthreads();

    float ps = 0.f;
    for (int n = tid; n < NS; n += 256) { float e = expf(w_s[n] - Mx); w_s[n] = e; ps += e; }
    rf[tid] = ps; __syncthreads();
    for (int s = 128; s > 0; s >>= 1) { if (tid < s) rf[tid] += rf[tid + s]; __syncthreads(); }
    const float S = rf[0];
    __syncthreads();

    float pm = 0.f;
    for (int n = tid; n < NS; n += 256) {
        float mw = m_s[n] ? (w_s[n] / S) : 0.f;
        w_s[n] = mw; pm += mw;
    }
    rf[tid] = pm; __syncthreads();
    for (int s = 128; s > 0; s >>= 1) { if (tid < s) rf[tid] += rf[tid + s]; __syncthreads(); }
    const float SM = rf[0];
    __syncthreads();

    // norm_w -> old (a_s);  w = clip(old, 0, UB)
    for (int n = tid; n < NS; n += 256) {
        float w0 = w_s[n] / (SM + 1e-8f);
        a_s[n] = w0;
        w_s[n] = fminf(fmaxf(w0, 0.f), UBv);
    }
    __syncthreads();

    // ---- 32-iter rebalance ----
    for (int it = 0; it < RITER; ++it) {
        float pl = 0.f, pn = 0.f; int ph = 0;
        for (int n = tid; n < NS; n += 256) {
            float w = w_s[n];
            int nm = (w != UBv) && m_s[n];
            pl += a_s[n] - w;
            if (nm) { pn += w; ph = 1; }
        }
        rf[tid] = pl; rb[tid] = pn; ri[tid] = ph;
        __syncthreads();
        for (int s = 128; s > 0; s >>= 1) {
            if (tid < s) { rf[tid] += rf[tid + s]; rb[tid] += rb[tid + s]; ri[tid] |= ri[tid + s]; }
            __syncthreads();
        }
        if (tid == 0) { sc[0] = rf[0]; sc[1] = rb[0]; sc[2] = ri[0] ? 1.f : 0.f; }
        __syncthreads();

        const float leftover = sc[0];
        const float nsum = sc[1];
        const bool hasnom = (sc[2] != 0.f);
        const bool done = (sc[4] != 0.f);
        const bool upd = (!done) && hasnom;
        const float denom = (nsum == 0.f) ? 1.f : nsum;

        int po = 0;
        for (int n = tid; n < NS; n += 256) {
            float w = w_s[n];
            int nm = (w != UBv) && m_s[n];
            float gift = (leftover * (nm ? w : 0.f)) / denom;
            float w1 = upd ? (w + gift) : w;
            if (w1 > UBv) po = 1;
            w_s[n] = w1;
            if (upd) a_s[n] = w1;
        }
        ri[tid] = po;
        __syncthreads();
        for (int s = 128; s > 0; s >>= 1) { if (tid < s) ri[tid] |= ri[tid + s]; __syncthreads(); }
        const bool over = (ri[0] != 0);
        __syncthreads();

        if (upd && over)
            for (int n = tid; n < NS; n += 256)
                w_s[n] = fminf(fmaxf(w_s[n], 0.f), UBv);
        if (tid == 0) {
            bool d = done || ((!done) && (!hasnom)) || (upd && (!over));
            sc[4] = d ? 1.f : 0.f;
        }
        __syncthreads();
    }

    for (int n = tid; n < NS; n += 256)
        out[(long long)b * NS + n] = w_s[n];
}

// ============================================================================
extern "C" void kernel_launch(void* const* d_in, const int* in_sizes, int n_in,
                              void* d_out, int out_size)
{
    (void)in_sizes; (void)n_in; (void)out_size;
    const float* x    = (const float*)d_in[0];
    const float* Wih0 = (const float*)d_in[1];
    const float* Whh0 = (const float*)d_in[2];
    const float* bih0 = (const float*)d_in[3];
    const float* bhh0 = (const float*)d_in[4];
    const float* Wih1 = (const float*)d_in[5];
    const float* Whh1 = (const float*)d_in[6];
    const float* bih1 = (const float*)d_in[7];
    const float* bhh1 = (const float*)d_in[8];
    const float* Wa   = (const float*)d_in[9];
    const float* ba   = (const float*)d_in[10];
    const float* Wf   = (const float*)d_in[11];
    const float* bf   = (const float*)d_in[12];
    float* out = (float*)d_out;

    float *xg, *hseq, *h1, *attb, *logb;
    cudaGetSymbolAddress((void**)&xg,   g_xg);
    cudaGetSymbolAddress((void**)&hseq, g_hseq);
    cudaGetSymbolAddress((void**)&h1,   g_h1);
    cudaGetSymbolAddress((void**)&attb, g_att);
    cudaGetSymbolAddress((void**)&logb, g_log);

    const int M = T_ * B_;   // 64000

    // xg0 = permute(x) @ Wih0^T + bih0     [T*B, 768]
    gemm_kernel<<<dim3(G3 / BN, M / BM), 256>>>(x, Wih0, bih0, xg, M, G3, NS, 1, 0);

    // GRU layer 0: write full hidden sequence
    for (int t = 0; t < T_; ++t) {
        const float* hin = t ? (hseq + (size_t)(t - 1) * B_ * H_) : nullptr;
        gru_step_kernel<<<dim3(16, 8), 128>>>(
            hin, Whh0, bhh0,
            xg + (size_t)t * B_ * G3,
            hseq + (size_t)t * B_ * H_);
    }

    // xg1 = hseq @ Wih1^T + bih1   (reuse g_xg)
    gemm_kernel<<<dim3(G3 / BN, M / BM), 256>>>(hseq, Wih1, bih1, xg, M, G3, H_, 0, 0);

    // GRU layer 1: ping-pong, keep only last h
    for (int t = 0; t < T_; ++t) {
        const float* hin = t ? (h1 + (size_t)((t - 1) & 1) * B_ * H_) : nullptr;
        gru_step_kernel<<<dim3(16, 8), 128>>>(
            hin, Whh1, bhh1,
            xg + (size_t)t * B_ * G3,
            h1 + (size_t)(t & 1) * B_ * H_);
    }
    const float* hT = h1 + (size_t)((T_ - 1) & 1) * B_ * H_;

    // att = sigmoid(hT @ Wa^T + ba);  logits = silu(hT @ Wf^T + bf)
    gemm_kernel<<<dim3(NS / BN, B_ / BM), 256>>>(hT, Wa, ba, attb, B_, NS, H_, 0, 1);
    gemm_kernel<<<dim3(NS / BN, B_ / BM), 256>>>(hT, Wf, bf, logb, B_, NS, H_, 0, 2);

    // top-50 + softmax + mask-normalize + rebalance
    finalize_kernel<<<B_, 256>>>(attb, logb, out);
}

// round 5
// speedup vs baseline: 1.0993x; 1.0993x over previous
#include <cuda_runtime.h>

#define B_   256
#define T_   250
#define NS   2048
#define H_   256
#define G3   768
#define NSEL 50
#define UBv  0.1f
#define RITER 32

// ---------------- scratch (device globals; no runtime alloc) ----------------
__device__ float g_xg[(size_t)T_ * B_ * G3];     // xg0, later reused as xg1
__device__ float g_hseq[(size_t)T_ * B_ * H_];   // hidden sequence (reused by layer 1)
__device__ float g_att[B_ * NS];
__device__ float g_log[B_ * NS];
__device__ unsigned long long g_cnt;             // grid-barrier counter

__device__ __forceinline__ float sigmf(float x) { return 1.f / (1.f + expf(-x)); }

// packed fp32x2 helpers (FFMA2 path — identical numerics to two fmaf's)
__device__ __forceinline__ unsigned long long dupf(float x) {
    unsigned long long r;
    asm("mov.b64 %0, {%1, %1};" : "=l"(r) : "f"(x));
    return r;
}
#define FFMA2(d, a, b) asm("fma.rn.f32x2 %0, %1, %2, %0;" : "+l"(d) : "l"(a), "l"(b))
__device__ __forceinline__ void unpack2(unsigned long long v, float& lo, float& hi) {
    asm("mov.b64 {%0, %1}, %2;" : "=f"(lo), "=f"(hi) : "l"(v));
}

// ============================================================================
// fp32 GEMM (FFMA2):  C[M,N] = act( A'[M,K] @ W[N,K]^T + bias[N] )
// permute=1: A row for output row m (= t*256+b) is x row b*250+t.
// BM=128, BN=64, BK=16, 256 threads, 8x4 micro-tile (packed pairs along M).
// ============================================================================
#define BM 128
#define BN 64
#define BK 16

__device__ __forceinline__ void gemm_tile_compute(
    const float (*__restrict__ As)[BM], const float (*__restrict__ Ws)[BN],
    unsigned long long acc2[4][4], int tm, int tn)
{
#pragma unroll
    for (int k = 0; k < BK; ++k) {
        ulonglong2 a01 = *(const ulonglong2*)&As[k][tm * 8];      // rows (0,1),(2,3)
        ulonglong2 a23 = *(const ulonglong2*)&As[k][tm * 8 + 4];  // rows (4,5),(6,7)
        float4 wv = *(const float4*)&Ws[k][tn * 4];
        unsigned long long w0 = dupf(wv.x), w1 = dupf(wv.y),
                           w2 = dupf(wv.z), w3 = dupf(wv.w);
        FFMA2(acc2[0][0], a01.x, w0); FFMA2(acc2[0][1], a01.x, w1);
        FFMA2(acc2[0][2], a01.x, w2); FFMA2(acc2[0][3], a01.x, w3);
        FFMA2(acc2[1][0], a01.y, w0); FFMA2(acc2[1][1], a01.y, w1);
        FFMA2(acc2[1][2], a01.y, w2); FFMA2(acc2[1][3], a01.y, w3);
        FFMA2(acc2[2][0], a23.x, w0); FFMA2(acc2[2][1], a23.x, w1);
        FFMA2(acc2[2][2], a23.x, w2); FFMA2(acc2[2][3], a23.x, w3);
        FFMA2(acc2[3][0], a23.y, w0); FFMA2(acc2[3][1], a23.y, w1);
        FFMA2(acc2[3][2], a23.y, w2); FFMA2(acc2[3][3], a23.y, w3);
    }
}

__global__ void __launch_bounds__(256) gemm_kernel(
    const float* __restrict__ A, const float* __restrict__ W,
    const float* __restrict__ bias, float* __restrict__ C,
    int M, int N, int K, int permute, int act)
{
    __shared__ float As[2][BK][BM];
    __shared__ float Ws[2][BK][BN];
    const int tid = threadIdx.x;
    const int m0 = blockIdx.y * BM;
    const int n0 = blockIdx.x * BN;

    const int lr = tid >> 2;          // 0..63
    const int lk = (tid & 3) << 2;    // 0,4,8,12

    const int mrow0 = m0 + lr;
    const int mrow1 = m0 + lr + 64;
    const long long arow0 = permute ? ((long long)(mrow0 & 255) * T_ + (mrow0 >> 8)) : (long long)mrow0;
    const long long arow1 = permute ? ((long long)(mrow1 & 255) * T_ + (mrow1 >> 8)) : (long long)mrow1;
    const float* pa0 = A + arow0 * K + lk;
    const float* pa1 = A + arow1 * K + lk;
    const float* pw  = W + (long long)(n0 + lr) * K + lk;

    const int tm = tid >> 4;   // 0..15
    const int tn = tid & 15;   // 0..15

    unsigned long long acc2[4][4];
#pragma unroll
    for (int i = 0; i < 4; ++i)
#pragma unroll
        for (int j = 0; j < 4; ++j) acc2[i][j] = 0ULL;

    {   // chunk 0
        float4 a0 = *(const float4*)pa0;
        float4 a1 = *(const float4*)pa1;
        float4 wv = *(const float4*)pw;
        float av0[4] = {a0.x, a0.y, a0.z, a0.w};
        float av1[4] = {a1.x, a1.y, a1.z, a1.w};
        float wvv[4] = {wv.x, wv.y, wv.z, wv.w};
#pragma unroll
        for (int j = 0; j < 4; ++j) {
            As[0][lk + j][lr]      = av0[j];
            As[0][lk + j][lr + 64] = av1[j];
            Ws[0][lk + j][lr]      = wvv[j];
        }
    }
    __syncthreads();

    const int nCh = K / BK;
    for (int c = 1; c < nCh; ++c) {
        const int off = c * BK;
        float4 na0 = *(const float4*)(pa0 + off);
        float4 na1 = *(const float4*)(pa1 + off);
        float4 nw  = *(const float4*)(pw + off);

        gemm_tile_compute(As[(c - 1) & 1], Ws[(c - 1) & 1], acc2, tm, tn);

        const int wb = c & 1;
        float av0[4] = {na0.x, na0.y, na0.z, na0.w};
        float av1[4] = {na1.x, na1.y, na1.z, na1.w};
        float wvv[4] = {nw.x, nw.y, nw.z, nw.w};
#pragma unroll
        for (int j = 0; j < 4; ++j) {
            As[wb][lk + j][lr]      = av0[j];
            As[wb][lk + j][lr + 64] = av1[j];
            Ws[wb][lk + j][lr]      = wvv[j];
        }
        __syncthreads();
    }
    gemm_tile_compute(As[(nCh - 1) & 1], Ws[(nCh - 1) & 1], acc2, tm, tn);

#pragma unroll
    for (int p = 0; p < 4; ++p) {
        float rowlo[4], rowhi[4];
#pragma unroll
        for (int j = 0; j < 4; ++j) {
            float lo, hi; unpack2(acc2[p][j], lo, hi);
            float bj = bias[n0 + tn * 4 + j];
            lo += bj; hi += bj;
            if (act == 1)      { lo = sigmf(lo); hi = sigmf(hi); }
            else if (act == 2) { lo = lo * sigmf(lo); hi = hi * sigmf(hi); }
            rowlo[j] = lo; rowhi[j] = hi;
        }
        const int mA = m0 + tm * 8 + 2 * p;
        float4 o0; o0.x = rowlo[0]; o0.y = rowlo[1]; o0.z = rowlo[2]; o0.w = rowlo[3];
        float4 o1; o1.x = rowhi[0]; o1.y = rowhi[1]; o1.z = rowhi[2]; o1.w = rowhi[3];
        *(float4*)&C[(long long)mA * N + n0 + tn * 4]       = o0;
        *(float4*)&C[(long long)(mA + 1) * N + n0 + tn * 4] = o1;
    }
}

// ============================================================================
// Persistent GRU scan: one launch runs all 250 steps of a layer.
// Grid 128 blocks (8 batch-tiles x 16 hcol-tiles) x 128 threads, all resident.
// Weights slice (48 rows x 256) cached in smem once; h-tile staged transposed.
// Grid barrier: monotonic counter (reset by a tiny kernel before each launch).
// Reads h_prev via __ldcg (L2), releases writes via __threadfence + atomicAdd.
// ============================================================================
#define GRU_SMEM ((3 * 256 * 16 + 256 * 36) * 4)

__global__ void __launch_bounds__(128, 1) gru_scan_kernel(
    const float* __restrict__ Whh, const float* __restrict__ bhh,
    const float* __restrict__ xg, float* __restrict__ hseq)
{
    extern __shared__ float sm[];
    float* w_s = sm;                     // [3*256][16]
    float* hT  = sm + 3 * 256 * 16;      // [256][36] transposed h tile

    const int tid = threadIdx.x;
    const int b0 = (blockIdx.x >> 4) * 32;    // batch tile base
    const int h0 = (blockIdx.x & 15) * 16;    // hcol tile base
    const int c  = tid & 15;                  // hcol within tile
    const int r0 = (tid >> 4) * 4;            // 4 batch rows per thread

    // one-time weight slice load: rows {h0+c, 256+h0+c, 512+h0+c} of Whh
    if (tid < 48) {
        const int g = tid / 16, cc = tid % 16;
        const float* wp = Whh + (size_t)(g * H_ + h0 + cc) * H_;
        for (int k = 0; k < H_; k += 4) {
            float4 wv = *(const float4*)(wp + k);
            w_s[((g << 8) + k + 0) * 16 + cc] = wv.x;
            w_s[((g << 8) + k + 1) * 16 + cc] = wv.y;
            w_s[((g << 8) + k + 2) * 16 + cc] = wv.z;
            w_s[((g << 8) + k + 3) * 16 + cc] = wv.w;
        }
    }
    __syncthreads();

    const int hg = h0 + c;
    const float br = bhh[hg], bz = bhh[H_ + hg], bn = bhh[2 * H_ + hg];
    const int lr  = tid & 31;         // h-load: row within batch tile
    const int lk0 = (tid >> 5) * 64;  // h-load: k chunk base

    for (int t = 0; t < T_; ++t) {
        unsigned long long ar[2] = {0ULL, 0ULL}, az[2] = {0ULL, 0ULL}, an[2] = {0ULL, 0ULL};
        float hold[4] = {0.f, 0.f, 0.f, 0.f};

        if (t > 0) {
            // stage h_prev tile transposed into smem (bypass L1: cross-block data)
            const float* src = hseq + (size_t)(t - 1) * (B_ * H_)
                                    + (size_t)(b0 + lr) * H_ + lk0;
#pragma unroll
            for (int q = 0; q < 16; ++q) {
                float4 v = __ldcg((const float4*)(src + q * 4));
                const int k = lk0 + q * 4;
                hT[(k + 0) * 36 + lr] = v.x;
                hT[(k + 1) * 36 + lr] = v.y;
                hT[(k + 2) * 36 + lr] = v.z;
                hT[(k + 3) * 36 + lr] = v.w;
            }
            __syncthreads();

#pragma unroll 4
            for (int k = 0; k < H_; ++k) {
                ulonglong2 av = *(const ulonglong2*)&hT[k * 36 + r0];
                unsigned long long wrd = dupf(w_s[k * 16 + c]);
                unsigned long long wzd = dupf(w_s[(256 + k) * 16 + c]);
                unsigned long long wnd = dupf(w_s[(512 + k) * 16 + c]);
                FFMA2(ar[0], av.x, wrd); FFMA2(ar[1], av.y, wrd);
                FFMA2(az[0], av.x, wzd); FFMA2(az[1], av.y, wzd);
                FFMA2(an[0], av.x, wnd); FFMA2(an[1], av.y, wnd);
            }
#pragma unroll
            for (int i = 0; i < 4; ++i) hold[i] = hT[hg * 36 + r0 + i];
        }

        // gates + write h(t)
        float arr[4], azz[4], ann[4];
        unpack2(ar[0], arr[0], arr[1]); unpack2(ar[1], arr[2], arr[3]);
        unpack2(az[0], azz[0], azz[1]); unpack2(az[1], azz[2], azz[3]);
        unpack2(an[0], ann[0], ann[1]); unpack2(an[1], ann[2], ann[3]);

        const float* xrow = xg + (size_t)t * (B_ * G3);
        float* hout = hseq + (size_t)t * (B_ * H_);
#pragma unroll
        for (int i = 0; i < 4; ++i) {
            const int b = b0 + r0 + i;
            const float* xr = xrow + (size_t)b * G3;
            const float r = sigmf(xr[hg] + arr[i] + br);
            const float z = sigmf(xr[H_ + hg] + azz[i] + bz);
            const float n = tanhf(xr[2 * H_ + hg] + r * (ann[i] + bn));
            hout[(size_t)b * H_ + hg] = (1.f - z) * n + z * hold[i];
        }

        if (t < T_ - 1) {
            __threadfence();          // release this thread's h writes
            __syncthreads();          // all threads' fences precede the arrive
            if (tid == 0) {
                atomicAdd(&g_cnt, 1ULL);
                const unsigned long long target =
                    (unsigned long long)(t + 1) * gridDim.x;
                volatile unsigned long long* p =
                    (volatile unsigned long long*)&g_cnt;
                while (*p < target) { }
                __threadfence();      // acquire
            }
            __syncthreads();
        }
    }
}

__global__ void reset_sync_kernel() { g_cnt = 0ULL; }

// ============================================================================
// Finalize per batch row: top-50 -> mask; softmax; mask+normalize; rebalance.
// ============================================================================
__global__ void __launch_bounds__(256) finalize_kernel(
    const float* __restrict__ att, const float* __restrict__ logits,
    float* __restrict__ out)
{
    __shared__ float a_s[NS];
    __shared__ float w_s[NS];
    __shared__ unsigned char m_s[NS];
    __shared__ float rf[256];
    __shared__ float rb[256];
    __shared__ int   ri[256];
    __shared__ float sc[8];

    const int b = blockIdx.x;
    const int tid = threadIdx.x;

    for (int n = tid; n < NS; n += 256) {
        a_s[n] = att[(long long)b * NS + n];
        w_s[n] = logits[(long long)b * NS + n];
        m_s[n] = 0;
    }
    if (tid == 0) sc[4] = 0.f;
    __syncthreads();

    for (int it = 0; it < NSEL; ++it) {
        float bv = -3.402823466e38f; int bi = 0x7fffffff;
        for (int n = tid; n < NS; n += 256) {
            float v = a_s[n];
            if (v > bv) { bv = v; bi = n; }
        }
        rf[tid] = bv; ri[tid] = bi;
        __syncthreads();
        for (int s = 128; s > 0; s >>= 1) {
            if (tid < s) {
                float v2 = rf[tid + s]; int i2 = ri[tid + s];
                if (v2 > rf[tid] || (v2 == rf[tid] && i2 < ri[tid])) { rf[tid] = v2; ri[tid] = i2; }
            }
            __syncthreads();
        }
        if (tid == 0) { m_s[ri[0]] = 1; a_s[ri[0]] = -3.402823466e38f; }
        __syncthreads();
    }

    float lm = -3.402823466e38f;
    for (int n = tid; n < NS; n += 256) lm = fmaxf(lm, w_s[n]);
    rf[tid] = lm; __syncthreads();
    for (int s = 128; s > 0; s >>= 1) { if (tid < s) rf[tid] = fmaxf(rf[tid], rf[tid + s]); __syncthreads(); }
    const float Mx = rf[0];
    __syncthreads();

    float ps = 0.f;
    for (int n = tid; n < NS; n += 256) { float e = expf(w_s[n] - Mx); w_s[n] = e; ps += e; }
    rf[tid] = ps; __syncthreads();
    for (int s = 128; s > 0; s >>= 1) { if (tid < s) rf[tid] += rf[tid + s]; __syncthreads(); }
    const float S = rf[0];
    __syncthreads();

    float pm = 0.f;
    for (int n = tid; n < NS; n += 256) {
        float mw = m_s[n] ? (w_s[n] / S) : 0.f;
        w_s[n] = mw; pm += mw;
    }
    rf[tid] = pm; __syncthreads();
    for (int s = 128; s > 0; s >>= 1) { if (tid < s) rf[tid] += rf[tid + s]; __syncthreads(); }
    const float SM = rf[0];
    __syncthreads();

    for (int n = tid; n < NS; n += 256) {
        float w0 = w_s[n] / (SM + 1e-8f);
        a_s[n] = w0;
        w_s[n] = fminf(fmaxf(w0, 0.f), UBv);
    }
    __syncthreads();

    for (int it = 0; it < RITER; ++it) {
        float pl = 0.f, pn = 0.f; int ph = 0;
        for (int n = tid; n < NS; n += 256) {
            float w = w_s[n];
            int nm = (w != UBv) && m_s[n];
            pl += a_s[n] - w;
            if (nm) { pn += w; ph = 1; }
        }
        rf[tid] = pl; rb[tid] = pn; ri[tid] = ph;
        __syncthreads();
        for (int s = 128; s > 0; s >>= 1) {
            if (tid < s) { rf[tid] += rf[tid + s]; rb[tid] += rb[tid + s]; ri[tid] |= ri[tid + s]; }
            __syncthreads();
        }
        if (tid == 0) { sc[0] = rf[0]; sc[1] = rb[0]; sc[2] = ri[0] ? 1.f : 0.f; }
        __syncthreads();

        const float leftover = sc[0];
        const float nsum = sc[1];
        const bool hasnom = (sc[2] != 0.f);
        const bool done = (sc[4] != 0.f);
        const bool upd = (!done) && hasnom;
        const float denom = (nsum == 0.f) ? 1.f : nsum;

        int po = 0;
        for (int n = tid; n < NS; n += 256) {
            float w = w_s[n];
            int nm = (w != UBv) && m_s[n];
            float gift = (leftover * (nm ? w : 0.f)) / denom;
            float w1 = upd ? (w + gift) : w;
            if (w1 > UBv) po = 1;
            w_s[n] = w1;
            if (upd) a_s[n] = w1;
        }
        ri[tid] = po;
        __syncthreads();
        for (int s = 128; s > 0; s >>= 1) { if (tid < s) ri[tid] |= ri[tid + s]; __syncthreads(); }
        const bool over = (ri[0] != 0);
        __syncthreads();

        if (upd && over)
            for (int n = tid; n < NS; n += 256)
                w_s[n] = fminf(fmaxf(w_s[n], 0.f), UBv);
        if (tid == 0) {
            bool d = done || ((!done) && (!hasnom)) || (upd && (!over));
            sc[4] = d ? 1.f : 0.f;
        }
        __syncthreads();
    }

    for (int n = tid; n < NS; n += 256)
        out[(long long)b * NS + n] = w_s[n];
}

// ============================================================================
extern "C" void kernel_launch(void* const* d_in, const int* in_sizes, int n_in,
                              void* d_out, int out_size)
{
    (void)in_sizes; (void)n_in; (void)out_size;
    const float* x    = (const float*)d_in[0];
    const float* Wih0 = (const float*)d_in[1];
    const float* Whh0 = (const float*)d_in[2];
    const float* bih0 = (const float*)d_in[3];
    const float* bhh0 = (const float*)d_in[4];
    const float* Wih1 = (const float*)d_in[5];
    const float* Whh1 = (const float*)d_in[6];
    const float* bih1 = (const float*)d_in[7];
    const float* bhh1 = (const float*)d_in[8];
    const float* Wa   = (const float*)d_in[9];
    const float* ba   = (const float*)d_in[10];
    const float* Wf   = (const float*)d_in[11];
    const float* bf   = (const float*)d_in[12];
    float* out = (float*)d_out;

    float *xg, *hseq, *attb, *logb;
    cudaGetSymbolAddress((void**)&xg,   g_xg);
    cudaGetSymbolAddress((void**)&hseq, g_hseq);
    cudaGetSymbolAddress((void**)&attb, g_att);
    cudaGetSymbolAddress((void**)&logb, g_log);

    static int smem_set = 0;
    if (!smem_set) {
        cudaFuncSetAttribute(gru_scan_kernel,
                             cudaFuncAttributeMaxDynamicSharedMemorySize, GRU_SMEM);
        smem_set = 1;
    }

    const int M = T_ * B_;   // 64000

    // xg0 = permute(x) @ Wih0^T + bih0     [T*B, 768]
    gemm_kernel<<<dim3(G3 / BN, M / BM), 256>>>(x, Wih0, bih0, xg, M, G3, NS, 1, 0);

    // GRU layer 0 (persistent): writes full hidden sequence into hseq
    reset_sync_kernel<<<1, 1>>>();
    gru_scan_kernel<<<128, 128, GRU_SMEM>>>(Whh0, bhh0, xg, hseq);

    // xg1 = hseq @ Wih1^T + bih1   (reuse g_xg)
    gemm_kernel<<<dim3(G3 / BN, M / BM), 256>>>(hseq, Wih1, bih1, xg, M, G3, H_, 0, 0);

    // GRU layer 1 (persistent): reuses hseq as its own sequence scratch
    reset_sync_kernel<<<1, 1>>>();
    gru_scan_kernel<<<128, 128, GRU_SMEM>>>(Whh1, bhh1, xg, hseq);

    const float* hT = hseq + (size_t)(T_ - 1) * B_ * H_;

    // att = sigmoid(hT @ Wa^T + ba);  logits = silu(hT @ Wf^T + bf)
    gemm_kernel<<<dim3(NS / BN, B_ / BM), 256>>>(hT, Wa, ba, attb, B_, NS, H_, 0, 1);
    gemm_kernel<<<dim3(NS / BN, B_ / BM), 256>>>(hT, Wf, bf, logb, B_, NS, H_, 0, 2);

    finalize_kernel<<<B_, 256>>>(attb, logb, out);
}

// round 6
// speedup vs baseline: 1.5437x; 1.4043x over previous
#include <cuda_runtime.h>

#define B_   256
#define T_   250
#define NS   2048
#define H_   256
#define G3   768
#define NSEL 50
#define UBv  0.1f
#define RITER 32

// ---------------- scratch (device globals; no runtime alloc) ----------------
__device__ float g_xg[(size_t)T_ * B_ * G3];     // xg0, later reused as xg1
__device__ float g_hseq[(size_t)T_ * B_ * H_];   // hidden sequence (reused by layer 1)
__device__ float g_att[B_ * NS];
__device__ float g_log[B_ * NS];
__device__ unsigned long long g_cnt;             // grid-barrier counter

__device__ __forceinline__ float sigmf(float x) { return 1.f / (1.f + expf(-x)); }

// packed fp32x2 helpers — identical numerics to two scalar rn-FMAs
__device__ __forceinline__ unsigned long long dupf(float x) {
    unsigned long long r;
    asm("mov.b64 %0, {%1, %1};" : "=l"(r) : "f"(x));
    return r;
}
#define FFMA2(d, a, b) asm("fma.rn.f32x2 %0, %1, %2, %0;" : "+l"(d) : "l"(a), "l"(b))
#define FADD2(d, a)    asm("add.rn.f32x2 %0, %0, %1;"     : "+l"(d) : "l"(a))
__device__ __forceinline__ void unpack2(unsigned long long v, float& lo, float& hi) {
    asm("mov.b64 {%0, %1}, %2;" : "=f"(lo), "=f"(hi) : "l"(v));
}

// ============================================================================
// fp32 GEMM (FFMA2):  C[M,N] = act( A'[M,K] @ W[N,K]^T + bias[N] )
// permute=1: A row for output row m (= t*256+b) is x row b*250+t.
// BM=128, BN=128, BK=16, 256 threads, 8x8 micro-tile (pairs packed along M).
// ============================================================================
#define BM 128
#define BN 128
#define BK 16
#define ASTR 132          // As row stride (floats) — 2-way store conflicts only
#define WSTR 140          // Ws row stride (floats)
// Ws column stagger: 16 float4's per row land on 2 bank phases instead of 4
__device__ __forceinline__ int wphys(int c) { return c + ((c >> 5) << 2); }

__device__ __forceinline__ void gemm_tile_compute(
    const float* __restrict__ As, const float* __restrict__ Ws,
    unsigned long long acc2[4][8], int tm, int wcol)
{
#pragma unroll
    for (int k = 0; k < BK; ++k) {
        ulonglong2 a01 = *(const ulonglong2*)&As[k * ASTR + tm * 8];
        ulonglong2 a23 = *(const ulonglong2*)&As[k * ASTR + tm * 8 + 4];
        float4 w0 = *(const float4*)&Ws[k * WSTR + wcol];
        float4 w1 = *(const float4*)&Ws[k * WSTR + wcol + 4];
        unsigned long long wd[8];
        wd[0] = dupf(w0.x); wd[1] = dupf(w0.y); wd[2] = dupf(w0.z); wd[3] = dupf(w0.w);
        wd[4] = dupf(w1.x); wd[5] = dupf(w1.y); wd[6] = dupf(w1.z); wd[7] = dupf(w1.w);
#pragma unroll
        for (int j = 0; j < 8; ++j) {
            FFMA2(acc2[0][j], a01.x, wd[j]);
            FFMA2(acc2[1][j], a01.y, wd[j]);
            FFMA2(acc2[2][j], a23.x, wd[j]);
            FFMA2(acc2[3][j], a23.y, wd[j]);
        }
    }
}

__global__ void __launch_bounds__(256, 2) gemm_kernel(
    const float* __restrict__ A, const float* __restrict__ W,
    const float* __restrict__ bias, float* __restrict__ C,
    int M, int N, int K, int permute, int act)
{
    __shared__ float As[2][BK * ASTR];
    __shared__ float Ws[2][BK * WSTR];
    const int tid = threadIdx.x;
    const int m0 = blockIdx.y * BM;
    const int n0 = blockIdx.x * BN;

    const int lr = tid >> 2;          // 0..63
    const int lk = (tid & 3) << 2;    // 0,4,8,12

    const int mrow0 = m0 + lr;
    const int mrow1 = m0 + lr + 64;
    const long long arow0 = permute ? ((long long)(mrow0 & 255) * T_ + (mrow0 >> 8)) : (long long)mrow0;
    const long long arow1 = permute ? ((long long)(mrow1 & 255) * T_ + (mrow1 >> 8)) : (long long)mrow1;
    const float* pa0 = A + arow0 * K + lk;
    const float* pa1 = A + arow1 * K + lk;
    const float* pw0 = W + (long long)(n0 + lr) * K + lk;
    const float* pw1 = W + (long long)(n0 + lr + 64) * K + lk;

    const int tm = tid >> 4;                 // 0..15 (row group of 8)
    const int tn = tid & 15;                 // 0..15 (col group of 8)
    const int wcol = tn * 8 + ((tn >> 2) << 2);  // = wphys(tn*8)
    const int wc0 = wphys(lr);
    const int wc1 = wphys(lr + 64);

    unsigned long long acc2[4][8];
#pragma unroll
    for (int i = 0; i < 4; ++i)
#pragma unroll
        for (int j = 0; j < 8; ++j) acc2[i][j] = 0ULL;

    {   // chunk 0
        float4 a0 = *(const float4*)pa0;
        float4 a1 = *(const float4*)pa1;
        float4 w0 = *(const float4*)pw0;
        float4 w1 = *(const float4*)pw1;
        float av0[4] = {a0.x, a0.y, a0.z, a0.w};
        float av1[4] = {a1.x, a1.y, a1.z, a1.w};
        float wv0[4] = {w0.x, w0.y, w0.z, w0.w};
        float wv1[4] = {w1.x, w1.y, w1.z, w1.w};
#pragma unroll
        for (int j = 0; j < 4; ++j) {
            As[0][(lk + j) * ASTR + lr]      = av0[j];
            As[0][(lk + j) * ASTR + lr + 64] = av1[j];
            Ws[0][(lk + j) * WSTR + wc0]     = wv0[j];
            Ws[0][(lk + j) * WSTR + wc1]     = wv1[j];
        }
    }
    __syncthreads();

    const int nCh = K / BK;
    for (int c = 1; c < nCh; ++c) {
        const int off = c * BK;
        float4 na0 = *(const float4*)(pa0 + off);
        float4 na1 = *(const float4*)(pa1 + off);
        float4 nw0 = *(const float4*)(pw0 + off);
        float4 nw1 = *(const float4*)(pw1 + off);

        gemm_tile_compute(As[(c - 1) & 1], Ws[(c - 1) & 1], acc2, tm, wcol);

        const int wb = c & 1;
        float av0[4] = {na0.x, na0.y, na0.z, na0.w};
        float av1[4] = {na1.x, na1.y, na1.z, na1.w};
        float wv0[4] = {nw0.x, nw0.y, nw0.z, nw0.w};
        float wv1[4] = {nw1.x, nw1.y, nw1.z, nw1.w};
#pragma unroll
        for (int j = 0; j < 4; ++j) {
            As[wb][(lk + j) * ASTR + lr]      = av0[j];
            As[wb][(lk + j) * ASTR + lr + 64] = av1[j];
            Ws[wb][(lk + j) * WSTR + wc0]     = wv0[j];
            Ws[wb][(lk + j) * WSTR + wc1]     = wv1[j];
        }
        __syncthreads();
    }
    gemm_tile_compute(As[(nCh - 1) & 1], Ws[(nCh - 1) & 1], acc2, tm, wcol);

    // epilogue: rows m0+tm*8+2p (lo) / +2p+1 (hi), cols n0+tn*8..+7
#pragma unroll
    for (int p = 0; p < 4; ++p) {
        float rowlo[8], rowhi[8];
#pragma unroll
        for (int j = 0; j < 8; ++j) {
            float lo, hi; unpack2(acc2[p][j], lo, hi);
            float bj = bias[n0 + tn * 8 + j];
            lo += bj; hi += bj;
            if (act == 1)      { lo = sigmf(lo); hi = sigmf(hi); }
            else if (act == 2) { lo = lo * sigmf(lo); hi = hi * sigmf(hi); }
            rowlo[j] = lo; rowhi[j] = hi;
        }
        const long long mA = m0 + tm * 8 + 2 * p;
        float* c0 = &C[mA * N + n0 + tn * 8];
        float* c1 = &C[(mA + 1) * N + n0 + tn * 8];
        *(float4*)c0       = make_float4(rowlo[0], rowlo[1], rowlo[2], rowlo[3]);
        *(float4*)(c0 + 4) = make_float4(rowlo[4], rowlo[5], rowlo[6], rowlo[7]);
        *(float4*)c1       = make_float4(rowhi[0], rowhi[1], rowhi[2], rowhi[3]);
        *(float4*)(c1 + 4) = make_float4(rowhi[4], rowhi[5], rowhi[6], rowhi[7]);
    }
}

// ============================================================================
// Persistent GRU scan: one launch runs all 250 steps of a layer.
// Grid 128 blocks = 8 batch-tiles(32) x 16 hcol-tiles(16); 256 threads/block:
//   c  = tid & 15        hcol within tile
//   g  = (tid>>4) & 3    row group (8 rows each)
//   ks = tid >> 6        k-quarter (64 k each)
// Weights pre-duplicated as f32x2 pairs in smem (no per-k dup movs).
// k-split partials reduced through smem; grid barrier via monotonic counter.
// ============================================================================
#define GRU_W2_ULL   (3 * 256 * 16)                 // 12288 ULL  (98304 B)
#define GRU_HT_F     (256 * 36)                     // 9216 f     (36864 B)
#define GRU_PART_ULL (3 * 64 * 12)                  // 2304 ULL   (18432 B)
#define GRU_SMEM     (GRU_W2_ULL * 8 + GRU_HT_F * 4 + GRU_PART_ULL * 8)  // 153600

__global__ void __launch_bounds__(256, 1) gru_scan_kernel(
    const float* __restrict__ Whh, const float* __restrict__ bhh,
    const float* __restrict__ xg, float* __restrict__ hseq)
{
    extern __shared__ char smraw[];
    unsigned long long* w2  = (unsigned long long*)smraw;                   // [3*256][16]
    float*              hT  = (float*)(smraw + GRU_W2_ULL * 8);             // [256][36]
    unsigned long long* prt = (unsigned long long*)(smraw + GRU_W2_ULL * 8 + GRU_HT_F * 4);

    const int tid = threadIdx.x;
    const int b0 = (blockIdx.x >> 4) * 32;
    const int h0 = (blockIdx.x & 15) * 16;
    const int c  = tid & 15;
    const int g  = (tid >> 4) & 3;
    const int ks = tid >> 6;
    const int r0 = g * 8;
    const int slot = (g << 4) | c;            // 0..63

    // ---- one-time weight load: rows {h0..h0+15} of each gate, duplicated ----
    for (int idx = tid; idx < 48 * 64; idx += 256) {
        const int row = idx >> 6;             // 0..47
        const int k4  = (idx & 63) << 2;
        const int gate = row >> 4, cc = row & 15;
        float4 wv = *(const float4*)(Whh + (size_t)(gate * H_ + h0 + cc) * H_ + k4);
        w2[(gate * 256 + k4 + 0) * 16 + cc] = dupf(wv.x);
        w2[(gate * 256 + k4 + 1) * 16 + cc] = dupf(wv.y);
        w2[(gate * 256 + k4 + 2) * 16 + cc] = dupf(wv.z);
        w2[(gate * 256 + k4 + 3) * 16 + cc] = dupf(wv.w);
    }
    __syncthreads();

    const int hg = h0 + c;
    const float br = bhh[hg], bz = bhh[H_ + hg], bn = bhh[2 * H_ + hg];
    const int lr  = tid & 31;          // staging: batch row in tile
    const int lk0 = (tid >> 5) * 32;   // staging: k chunk base

    for (int t = 0; t < T_; ++t) {
        unsigned long long aR[4] = {0, 0, 0, 0}, aZ[4] = {0, 0, 0, 0}, aN[4] = {0, 0, 0, 0};
        float xv[3][8];

        // prefetch xg gate inputs (ks==0 threads do the epilogue)
        if (ks == 0) {
            const float* xrow = xg + (size_t)t * (B_ * G3);
#pragma unroll
            for (int i = 0; i < 8; ++i) {
                const float* xr = xrow + (size_t)(b0 + r0 + i) * G3;
                xv[0][i] = xr[hg];
                xv[1][i] = xr[H_ + hg];
                xv[2][i] = xr[2 * H_ + hg];
            }
        }

        if (t > 0) {
            // stage h_prev tile transposed (L2 reads: cross-block data)
            const float* src = hseq + (size_t)(t - 1) * (B_ * H_)
                                    + (size_t)(b0 + lr) * H_ + lk0;
#pragma unroll
            for (int q = 0; q < 8; ++q) {
                float4 v = __ldcg((const float4*)(src + q * 4));
                const int k = lk0 + q * 4;
                hT[(k + 0) * 36 + lr] = v.x;
                hT[(k + 1) * 36 + lr] = v.y;
                hT[(k + 2) * 36 + lr] = v.z;
                hT[(k + 3) * 36 + lr] = v.w;
            }
            __syncthreads();

            const int kb = ks * 64;
#pragma unroll 4
            for (int kk = 0; kk < 64; ++kk) {
                const int k = kb + kk;
                ulonglong2 a01 = *(const ulonglong2*)&hT[k * 36 + r0];
                ulonglong2 a23 = *(const ulonglong2*)&hT[k * 36 + r0 + 4];
                unsigned long long wr = w2[k * 16 + c];
                unsigned long long wz = w2[(256 + k) * 16 + c];
                unsigned long long wn = w2[(512 + k) * 16 + c];
                FFMA2(aR[0], a01.x, wr); FFMA2(aR[1], a01.y, wr);
                FFMA2(aR[2], a23.x, wr); FFMA2(aR[3], a23.y, wr);
                FFMA2(aZ[0], a01.x, wz); FFMA2(aZ[1], a01.y, wz);
                FFMA2(aZ[2], a23.x, wz); FFMA2(aZ[3], a23.y, wz);
                FFMA2(aN[0], a01.x, wn); FFMA2(aN[1], a01.y, wn);
                FFMA2(aN[2], a23.x, wn); FFMA2(aN[3], a23.y, wn);
            }

            if (ks != 0) {
                unsigned long long* p = prt + ((ks - 1) * 64 + slot) * 12;
#pragma unroll
                for (int i = 0; i < 4; ++i) { p[i] = aR[i]; p[4 + i] = aZ[i]; p[8 + i] = aN[i]; }
            }
            __syncthreads();
            if (ks == 0) {
#pragma unroll
                for (int q = 0; q < 3; ++q) {
                    const unsigned long long* p = prt + (q * 64 + slot) * 12;
#pragma unroll
                    for (int i = 0; i < 4; ++i) {
                        FADD2(aR[i], p[i]); FADD2(aZ[i], p[4 + i]); FADD2(aN[i], p[8 + i]);
                    }
                }
            }
        }

        if (ks == 0) {
            float rr[8], zz[8], nn[8], hold[8];
#pragma unroll
            for (int i = 0; i < 4; ++i) {
                unpack2(aR[i], rr[2 * i], rr[2 * i + 1]);
                unpack2(aZ[i], zz[2 * i], zz[2 * i + 1]);
                unpack2(aN[i], nn[2 * i], nn[2 * i + 1]);
            }
#pragma unroll
            for (int i = 0; i < 8; ++i)
                hold[i] = (t > 0) ? hT[hg * 36 + r0 + i] : 0.f;

            float* hout = hseq + (size_t)t * (B_ * H_);
#pragma unroll
            for (int i = 0; i < 8; ++i) {
                const float r = sigmf(xv[0][i] + rr[i] + br);
                const float z = sigmf(xv[1][i] + zz[i] + bz);
                const float n = tanhf(xv[2][i] + r * (nn[i] + bn));
                hout[(size_t)(b0 + r0 + i) * H_ + hg] = (1.f - z) * n + z * hold[i];
            }
        }

        if (t < T_ - 1) {
            __threadfence();
            __syncthreads();
            if (tid == 0) {
                atomicAdd(&g_cnt, 1ULL);
                const unsigned long long target =
                    (unsigned long long)(t + 1) * gridDim.x;
                volatile unsigned long long* p = (volatile unsigned long long*)&g_cnt;
                while (*p < target) { }
                __threadfence();
            }
            __syncthreads();
        }
    }
}

__global__ void reset_sync_kernel() { g_cnt = 0ULL; }

// ============================================================================
// Finalize per batch row: top-50 -> mask; softmax; mask+normalize; rebalance.
// ============================================================================
__global__ void __launch_bounds__(256) finalize_kernel(
    const float* __restrict__ att, const float* __restrict__ logits,
    float* __restrict__ out)
{
    __shared__ float a_s[NS];
    __shared__ float w_s[NS];
    __shared__ unsigned char m_s[NS];
    __shared__ float rf[256];
    __shared__ float rb[256];
    __shared__ int   ri[256];
    __shared__ float sc[8];

    const int b = blockIdx.x;
    const int tid = threadIdx.x;

    for (int n = tid; n < NS; n += 256) {
        a_s[n] = att[(long long)b * NS + n];
        w_s[n] = logits[(long long)b * NS + n];
        m_s[n] = 0;
    }
    if (tid == 0) sc[4] = 0.f;
    __syncthreads();

    for (int it = 0; it < NSEL; ++it) {
        float bv = -3.402823466e38f; int bi = 0x7fffffff;
        for (int n = tid; n < NS; n += 256) {
            float v = a_s[n];
            if (v > bv) { bv = v; bi = n; }
        }
        rf[tid] = bv; ri[tid] = bi;
        __syncthreads();
        for (int s = 128; s > 0; s >>= 1) {
            if (tid < s) {
                float v2 = rf[tid + s]; int i2 = ri[tid + s];
                if (v2 > rf[tid] || (v2 == rf[tid] && i2 < ri[tid])) { rf[tid] = v2; ri[tid] = i2; }
            }
            __syncthreads();
        }
        if (tid == 0) { m_s[ri[0]] = 1; a_s[ri[0]] = -3.402823466e38f; }
        __syncthreads();
    }

    float lm = -3.402823466e38f;
    for (int n = tid; n < NS; n += 256) lm = fmaxf(lm, w_s[n]);
    rf[tid] = lm; __syncthreads();
    for (int s = 128; s > 0; s >>= 1) { if (tid < s) rf[tid] = fmaxf(rf[tid], rf[tid + s]); __syncthreads(); }
    const float Mx = rf[0];
    __syncthreads();

    float ps = 0.f;
    for (int n = tid; n < NS; n += 256) { float e = expf(w_s[n] - Mx); w_s[n] = e; ps += e; }
    rf[tid] = ps; __syncthreads();
    for (int s = 128; s > 0; s >>= 1) { if (tid < s) rf[tid] += rf[tid + s]; __syncthreads(); }
    const float S = rf[0];
    __syncthreads();

    float pm = 0.f;
    for (int n = tid; n < NS; n += 256) {
        float mw = m_s[n] ? (w_s[n] / S) : 0.f;
        w_s[n] = mw; pm += mw;
    }
    rf[tid] = pm; __syncthreads();
    for (int s = 128; s > 0; s >>= 1) { if (tid < s) rf[tid] += rf[tid + s]; __syncthreads(); }
    const float SM = rf[0];
    __syncthreads();

    for (int n = tid; n < NS; n += 256) {
        float w0 = w_s[n] / (SM + 1e-8f);
        a_s[n] = w0;
        w_s[n] = fminf(fmaxf(w0, 0.f), UBv);
    }
    __syncthreads();

    for (int it = 0; it < RITER; ++it) {
        float pl = 0.f, pn = 0.f; int ph = 0;
        for (int n = tid; n < NS; n += 256) {
            float w = w_s[n];
            int nm = (w != UBv) && m_s[n];
            pl += a_s[n] - w;
            if (nm) { pn += w; ph = 1; }
        }
        rf[tid] = pl; rb[tid] = pn; ri[tid] = ph;
        __syncthreads();
        for (int s = 128; s > 0; s >>= 1) {
            if (tid < s) { rf[tid] += rf[tid + s]; rb[tid] += rb[tid + s]; ri[tid] |= ri[tid + s]; }
            __syncthreads();
        }
        if (tid == 0) { sc[0] = rf[0]; sc[1] = rb[0]; sc[2] = ri[0] ? 1.f : 0.f; }
        __syncthreads();

        const float leftover = sc[0];
        const float nsum = sc[1];
        const bool hasnom = (sc[2] != 0.f);
        const bool done = (sc[4] != 0.f);
        const bool upd = (!done) && hasnom;
        const float denom = (nsum == 0.f) ? 1.f : nsum;

        int po = 0;
        for (int n = tid; n < NS; n += 256) {
            float w = w_s[n];
            int nm = (w != UBv) && m_s[n];
            float gift = (leftover * (nm ? w : 0.f)) / denom;
            float w1 = upd ? (w + gift) : w;
            if (w1 > UBv) po = 1;
            w_s[n] = w1;
            if (upd) a_s[n] = w1;
        }
        ri[tid] = po;
        __syncthreads();
        for (int s = 128; s > 0; s >>= 1) { if (tid < s) ri[tid] |= ri[tid + s]; __syncthreads(); }
        const bool over = (ri[0] != 0);
        __syncthreads();

        if (upd && over)
            for (int n = tid; n < NS; n += 256)
                w_s[n] = fminf(fmaxf(w_s[n], 0.f), UBv);
        if (tid == 0) {
            bool d = done || ((!done) && (!hasnom)) || (upd && (!over));
            sc[4] = d ? 1.f : 0.f;
        }
        __syncthreads();
    }

    for (int n = tid; n < NS; n += 256)
        out[(long long)b * NS + n] = w_s[n];
}

// ============================================================================
extern "C" void kernel_launch(void* const* d_in, const int* in_sizes, int n_in,
                              void* d_out, int out_size)
{
    (void)in_sizes; (void)n_in; (void)out_size;
    const float* x    = (const float*)d_in[0];
    const float* Wih0 = (const float*)d_in[1];
    const float* Whh0 = (const float*)d_in[2];
    const float* bih0 = (const float*)d_in[3];
    const float* bhh0 = (const float*)d_in[4];
    const float* Wih1 = (const float*)d_in[5];
    const float* Whh1 = (const float*)d_in[6];
    const float* bih1 = (const float*)d_in[7];
    const float* bhh1 = (const float*)d_in[8];
    const float* Wa   = (const float*)d_in[9];
    const float* ba   = (const float*)d_in[10];
    const float* Wf   = (const float*)d_in[11];
    const float* bf   = (const float*)d_in[12];
    float* out = (float*)d_out;

    float *xg, *hseq, *attb, *logb;
    cudaGetSymbolAddress((void**)&xg,   g_xg);
    cudaGetSymbolAddress((void**)&hseq, g_hseq);
    cudaGetSymbolAddress((void**)&attb, g_att);
    cudaGetSymbolAddress((void**)&logb, g_log);

    cudaFuncSetAttribute(gru_scan_kernel,
                         cudaFuncAttributeMaxDynamicSharedMemorySize, GRU_SMEM);

    const int M = T_ * B_;   // 64000

    // xg0 = permute(x) @ Wih0^T + bih0     [T*B, 768]
    gemm_kernel<<<dim3(G3 / BN, M / BM), 256>>>(x, Wih0, bih0, xg, M, G3, NS, 1, 0);

    // GRU layer 0 (persistent)
    reset_sync_kernel<<<1, 1>>>();
    gru_scan_kernel<<<128, 256, GRU_SMEM>>>(Whh0, bhh0, xg, hseq);

    // xg1 = hseq @ Wih1^T + bih1   (reuse g_xg)
    gemm_kernel<<<dim3(G3 / BN, M / BM), 256>>>(hseq, Wih1, bih1, xg, M, G3, H_, 0, 0);

    // GRU layer 1 (persistent): reuses hseq as its own sequence scratch
    reset_sync_kernel<<<1, 1>>>();
    gru_scan_kernel<<<128, 256, GRU_SMEM>>>(Whh1, bhh1, xg, hseq);

    const float* hT = hseq + (size_t)(T_ - 1) * B_ * H_;

    // att = sigmoid(hT @ Wa^T + ba);  logits = silu(hT @ Wf^T + bf)
    gemm_kernel<<<dim3(NS / BN, B_ / BM), 256>>>(hT, Wa, ba, attb, B_, NS, H_, 0, 1);
    gemm_kernel<<<dim3(NS / BN, B_ / BM), 256>>>(hT, Wf, bf, logb, B_, NS, H_, 0, 2);

    finalize_kernel<<<B_, 256>>>(attb, logb, out);
}